// round 3
// baseline (speedup 1.0000x reference)
#include <cuda_runtime.h>

// Problem constants (fixed shapes for this problem instance)
constexpr int Tn = 1000;   // timesteps
constexpr int Dd = 64;     // input dim
constexpr int Nn = 128;    // neurons
constexpr int Bb = 1000;   // batch rows

// Scratch: per-step input currents inp_cur[t][n] = input_signal[t,:] @ input_weights[:,n]
__device__ float g_inp_cur[Tn * Nn];

// ---------------------------------------------------------------------------
// Kernel A: tiny GEMM (1000x64 @ 64x128) -> g_inp_cur. Negligible cost.
// ---------------------------------------------------------------------------
__global__ void inp_cur_kernel(const float* __restrict__ sig,
                               const float* __restrict__ w_in) {
    int t = blockIdx.x;
    int n = threadIdx.x;
    float acc = 0.f;
#pragma unroll
    for (int d = 0; d < Dd; ++d)
        acc += sig[t * Dd + d] * w_in[d * Nn + n];
    g_inp_cur[t * Nn + n] = acc;
}

// Packed f32x2 add on raw 64-bit accumulators (1 SASS instr vs 2 FADD).
__device__ __forceinline__ void fadd2(unsigned long long& acc,
                                      unsigned long long w) {
    asm("add.rn.f32x2 %0, %0, %1;" : "+l"(acc) : "l"(w));
}

// ---------------------------------------------------------------------------
// Kernel B: one row per CTA, 2 warps per row (64 threads), grid = 1000.
//   - Warp h owns neurons [64h, 64h+64); lane l owns 64h+2l, 64h+2l+1.
//   - W_rec read through L1 via __ldg (64KB, resident after first pass).
//   - rec_t = trace_t @ W maintained incrementally via sparse spike masks:
//       rec = 0.95*rec + sum_{k in spikes} W[k][my 2 cols]
//     with software-pipelined loads + packed f32x2 accumulation.
//   - Spike masks exchanged between the row's two warps through 32B of static
//     SMEM, double-buffered by (t&1), one __syncthreads per step.
// ---------------------------------------------------------------------------
__global__ __launch_bounds__(64, 12)
void sim_kernel(const float* __restrict__ Wrec, float* __restrict__ out) {
    __shared__ unsigned smask[2][2][2];  // [buf][warp][word]

    const int tid  = threadIdx.x;
    const int half = tid >> 5;          // which 64-neuron half this warp owns
    const int lane = tid & 31;
    const int row  = blockIdx.x;        // 0..999
    const int colv = half * 32 + lane;  // float2 column index (0..63)
    const int peer = half ^ 1;

    float2* __restrict__ out_spk =
        reinterpret_cast<float2*>(out + (size_t)row * Tn * Nn);
    float2* __restrict__ out_mem =
        reinterpret_cast<float2*>(out + (size_t)Bb * Tn * Nn + (size_t)row * Tn * Nn);
    float2* __restrict__ out_trc =
        reinterpret_cast<float2*>(out + (size_t)2 * Bb * Tn * Nn + (size_t)row * Nn);

    // W as 64-bit words: row k, float2-column colv  ->  W2[(k<<6) + colv]
    const unsigned long long* __restrict__ W2 =
        reinterpret_cast<const unsigned long long*>(Wrec);

    float2 mem  = {0.f, 0.f};
    float2 syn  = {0.f, 0.f};
    float2 refr = {0.f, 0.f};
    float2 rec  = {0.f, 0.f};   // = trace_{t-1} @ W (incremental), my 2 cols
    float2 trc  = {0.f, 0.f};

    const float2* __restrict__ xin2 = reinterpret_cast<const float2*>(g_inp_cur);
    float2 x = xin2[colv];      // t = 0 input current (my 2 cols)

    const int mybase = half * 64;   // my warp's neuron base
    const int pbase  = mybase ^ 64; // peer warp's neuron base

    for (int t = 0; t < Tn; ++t) {
        // Prefetch next step's input current (L2-resident, shared by all rows)
        const int tnext = (t + 1 < Tn) ? (t + 1) : (Tn - 1);
        const float2 xnext = __ldg(&xin2[tnext * (Nn / 2) + colv]);

        // ---- Update my 2 neurons ----
        syn.x = syn.x * 0.8f + (x.x + rec.x);
        syn.y = syn.y * 0.8f + (x.y + rec.y);
        mem.x = mem.x * 0.9f + syn.x * 0.1f;
        mem.y = mem.y * 0.9f + syn.y * 0.1f;
        mem.x = (refr.x > 0.f) ? 0.f : mem.x;
        mem.y = (refr.y > 0.f) ? 0.f : mem.y;
        refr.x = fmaxf(refr.x - 1.f, 0.f);
        refr.y = fmaxf(refr.y - 1.f, 0.f);
        const bool k0 = mem.x > 1.0f;
        const bool k1 = mem.y > 1.0f;
        const float s0 = k0 ? 1.f : 0.f;
        const float s1 = k1 ? 1.f : 0.f;
        mem.x = k0 ? 0.f : mem.x;
        mem.y = k1 ? 0.f : mem.y;
        refr.x += s0 * 2.f;
        refr.y += s1 * 2.f;
        trc.x = trc.x * 0.95f + s0;
        trc.y = trc.y * 0.95f + s1;

        // ---- Exchange spike masks with peer warp ----
        // bit l of word j  <->  neuron 64*half + 2l + j
        const unsigned m0 = __ballot_sync(0xFFFFFFFFu, k0);
        const unsigned m1 = __ballot_sync(0xFFFFFFFFu, k1);
        const int buf = t & 1;
        if (lane == 0) {
            smask[buf][half][0] = m0;
            smask[buf][half][1] = m1;
        }
        __syncthreads();
        const unsigned p0 = smask[buf][peer][0];
        const unsigned p1 = smask[buf][peer][1];

        // ---- Coalesced 256B stores per warp (spikes, membrane) ----
        out_spk[t * (Nn / 2) + colv] = make_float2(s0, s1);
        out_mem[t * (Nn / 2) + colv] = mem;

        // ---- Incremental recurrent update over 4 spike-mask words ----
        // Software-pipelined: next W row load overlaps current accumulate.
        unsigned long long acc = 0ULL;  // packed (0.f, 0.f)
        {
            unsigned m;
            int base, j;

            m = m0; base = mybase; j = 0;
            if (m) {
                int l = __ffs(m) - 1; m &= m - 1;
                unsigned long long w = __ldg(&W2[((base + 2 * l + j) << 6) + colv]);
                while (m) {
                    int l2 = __ffs(m) - 1; m &= m - 1;
                    unsigned long long w2 = __ldg(&W2[((base + 2 * l2 + j) << 6) + colv]);
                    fadd2(acc, w);
                    w = w2;
                }
                fadd2(acc, w);
            }
            m = m1; j = 1;
            if (m) {
                int l = __ffs(m) - 1; m &= m - 1;
                unsigned long long w = __ldg(&W2[((base + 2 * l + j) << 6) + colv]);
                while (m) {
                    int l2 = __ffs(m) - 1; m &= m - 1;
                    unsigned long long w2 = __ldg(&W2[((base + 2 * l2 + j) << 6) + colv]);
                    fadd2(acc, w);
                    w = w2;
                }
                fadd2(acc, w);
            }
            m = p0; base = pbase; j = 0;
            if (m) {
                int l = __ffs(m) - 1; m &= m - 1;
                unsigned long long w = __ldg(&W2[((base + 2 * l + j) << 6) + colv]);
                while (m) {
                    int l2 = __ffs(m) - 1; m &= m - 1;
                    unsigned long long w2 = __ldg(&W2[((base + 2 * l2 + j) << 6) + colv]);
                    fadd2(acc, w);
                    w = w2;
                }
                fadd2(acc, w);
            }
            m = p1; j = 1;
            if (m) {
                int l = __ffs(m) - 1; m &= m - 1;
                unsigned long long w = __ldg(&W2[((base + 2 * l + j) << 6) + colv]);
                while (m) {
                    int l2 = __ffs(m) - 1; m &= m - 1;
                    unsigned long long w2 = __ldg(&W2[((base + 2 * l2 + j) << 6) + colv]);
                    fadd2(acc, w);
                    w = w2;
                }
                fadd2(acc, w);
            }
        }

        const float ax = __int_as_float((int)(acc & 0xFFFFFFFFULL));
        const float ay = __int_as_float((int)(acc >> 32));
        rec.x = rec.x * 0.95f + ax;
        rec.y = rec.y * 0.95f + ay;

        x = xnext;
    }

    // Final trace output (B, N)
    out_trc[colv] = trc;
}

// ---------------------------------------------------------------------------
// Harness entry
// ---------------------------------------------------------------------------
extern "C" void kernel_launch(void* const* d_in, const int* in_sizes, int n_in,
                              void* d_out, int out_size) {
    const float* sig   = (const float*)d_in[0];  // (1000, 64)
    const float* w_in  = (const float*)d_in[1];  // (64, 128)
    const float* w_rec = (const float*)d_in[2];  // (128, 128)
    float* out = (float*)d_out;
    (void)in_sizes; (void)n_in; (void)out_size;

    inp_cur_kernel<<<Tn, Nn>>>(sig, w_in);
    sim_kernel<<<Bb, 64>>>(w_rec, out);
}

// round 4
// speedup vs baseline: 1.3344x; 1.3344x over previous
#include <cuda_runtime.h>

// Problem constants (fixed shapes for this problem instance)
constexpr int Tn = 1000;   // timesteps
constexpr int Dd = 64;     // input dim
constexpr int Nn = 128;    // neurons
constexpr int Bb = 1000;   // batch rows
constexpr int GRID  = 296; // exactly 2 CTAs per SM (148 SMs)
constexpr int SLOTS = 4;   // row-slots per CTA (some inactive; rows = bid + 296*slot)
constexpr int THREADS = SLOTS * 64;  // 256

typedef unsigned long long ull;

// Scratch: per-step input currents inp_cur[t][n] = input_signal[t,:] @ input_weights[:,n]
__device__ float g_inp_cur[Tn * Nn];

// ---------------------------------------------------------------------------
// Kernel A: tiny GEMM (1000x64 @ 64x128) -> g_inp_cur. Negligible cost.
// ---------------------------------------------------------------------------
__global__ void inp_cur_kernel(const float* __restrict__ sig,
                               const float* __restrict__ w_in) {
    int t = blockIdx.x;
    int n = threadIdx.x;
    float acc = 0.f;
#pragma unroll
    for (int d = 0; d < Dd; ++d)
        acc += sig[t * Dd + d] * w_in[d * Nn + n];
    g_inp_cur[t * Nn + n] = acc;
}

// Packed f32x2 add on raw 64-bit accumulators (1 SASS instr vs 2 FADD).
__device__ __forceinline__ void fadd2(ull& acc, ull w) {
    asm("add.rn.f32x2 %0, %0, %1;" : "+l"(acc) : "l"(w));
}

// ---------------------------------------------------------------------------
// Kernel B: 2 warps per row; 4 row-slots per CTA; grid = 296 (2 CTAs/SM).
//   Rows for CTA b: { b, b+296, b+592, b+888(<1000) } -> every SM <= 7 rows.
//   - Warp h of a pair owns neurons [64h, 64h+64); lane l owns 64h+2l, +1.
//   - W_rec (128x128 fp32 = 64KB) in dynamic SMEM, shared by the whole CTA.
//   - rec_t = trace_t @ W maintained incrementally via sparse spike masks:
//       rec = 0.95*rec + sum_{k in spikes} W[k][my 2 cols]
//     spike loop: popc-counted, unrolled x2, dual packed accumulators.
//   - Masks exchanged via 8B packed STS, double-buffered, one named barrier
//     (64 threads, per row pair) per step.
// ---------------------------------------------------------------------------
__global__ __launch_bounds__(THREADS, 2)
void sim_kernel(const float* __restrict__ Wrec, float* __restrict__ out) {
    extern __shared__ float sW[];            // Nn*Nn floats = 64KB
    __shared__ ull smask[2][SLOTS][2];       // [buf][slot][half] -> {m0 | m1<<32}

    const int tid = threadIdx.x;
    // Cooperative vectorized load of W_rec into SMEM
    {
        const float4* src = reinterpret_cast<const float4*>(Wrec);
        float4* dst = reinterpret_cast<float4*>(sW);
        for (int i = tid; i < (Nn * Nn) / 4; i += THREADS) dst[i] = src[i];
    }
    __syncthreads();

    const int warp = tid >> 5;
    const int lane = tid & 31;
    const int rloc = warp >> 1;         // row slot within CTA (0..3)
    const int half = warp & 1;          // which 64-neuron half this warp owns
    const int row  = blockIdx.x + GRID * rloc;
    if (row >= Bb) return;              // inactive slot (whole pair exits)

    const int colv  = half * 32 + lane; // float2 column index (0..63)
    const int barid = rloc + 1;         // named barrier per row pair
    const int mybase = half * 64;
    const int pbase  = mybase ^ 64;

    float2* __restrict__ out_spk =
        reinterpret_cast<float2*>(out + (size_t)row * Tn * Nn);
    float2* __restrict__ out_mem =
        reinterpret_cast<float2*>(out + (size_t)Bb * Tn * Nn + (size_t)row * Tn * Nn);
    float2* __restrict__ out_trc =
        reinterpret_cast<float2*>(out + (size_t)2 * Bb * Tn * Nn + (size_t)row * Nn);

    // W as packed 64-bit words, pre-offset by this lane's column pair:
    //   row k -> wcol[k * 64]
    const ull* __restrict__ wcol = reinterpret_cast<const ull*>(sW) + colv;

    float2 mem  = {0.f, 0.f};
    float2 syn  = {0.f, 0.f};
    float2 refr = {0.f, 0.f};
    float2 rec  = {0.f, 0.f};
    float2 trc  = {0.f, 0.f};

    const float2* __restrict__ xin2 = reinterpret_cast<const float2*>(g_inp_cur);
    float2 x = xin2[colv];

    for (int t = 0; t < Tn; ++t) {
        const int tnext = (t + 1 < Tn) ? (t + 1) : (Tn - 1);
        const float2 xnext = __ldg(&xin2[tnext * (Nn / 2) + colv]);

        // ---- Update my 2 neurons ----
        syn.x = syn.x * 0.8f + (x.x + rec.x);
        syn.y = syn.y * 0.8f + (x.y + rec.y);
        mem.x = mem.x * 0.9f + syn.x * 0.1f;
        mem.y = mem.y * 0.9f + syn.y * 0.1f;
        mem.x = (refr.x > 0.f) ? 0.f : mem.x;
        mem.y = (refr.y > 0.f) ? 0.f : mem.y;
        refr.x = fmaxf(refr.x - 1.f, 0.f);
        refr.y = fmaxf(refr.y - 1.f, 0.f);
        const bool k0 = mem.x > 1.0f;
        const bool k1 = mem.y > 1.0f;
        const float s0 = k0 ? 1.f : 0.f;
        const float s1 = k1 ? 1.f : 0.f;
        mem.x = k0 ? 0.f : mem.x;
        mem.y = k1 ? 0.f : mem.y;
        refr.x += s0 * 2.f;
        refr.y += s1 * 2.f;
        trc.x = trc.x * 0.95f + s0;
        trc.y = trc.y * 0.95f + s1;

        // ---- Exchange spike masks with peer warp (8B packed) ----
        // bit l of word j  <->  neuron 64*half + 2l + j
        const unsigned m0 = __ballot_sync(0xFFFFFFFFu, k0);
        const unsigned m1 = __ballot_sync(0xFFFFFFFFu, k1);
        const int buf = t & 1;
        if (lane == 0)
            smask[buf][rloc][half] = ((ull)m1 << 32) | (ull)m0;
        asm volatile("bar.sync %0, 64;" :: "r"(barid) : "memory");
        const ull pm = smask[buf][rloc][half ^ 1];
        const unsigned p0 = (unsigned)pm;
        const unsigned p1 = (unsigned)(pm >> 32);

        // ---- Coalesced 256B stores per warp (spikes, membrane) ----
        out_spk[t * (Nn / 2) + colv] = make_float2(s0, s1);
        out_mem[t * (Nn / 2) + colv] = mem;

        // ---- Incremental recurrent update over 4 spike-mask words ----
        // k = base + 2l + j  ->  wcol[k*64] = wcol[(base+j)*64 + l*128]
        ull accA = 0ULL, accB = 0ULL;  // two chains for FADD ILP
#pragma unroll
        for (int w4 = 0; w4 < 4; ++w4) {
            unsigned m = (w4 == 0) ? m0 : (w4 == 1) ? m1 : (w4 == 2) ? p0 : p1;
            const int base = (w4 < 2) ? mybase : pbase;
            const int j    = w4 & 1;
            const ull* __restrict__ wp = wcol + (base + j) * 64;
            int c = __popc(m);
            for (int i = c >> 1; i > 0; --i) {
                const int l1 = __ffs(m) - 1; m &= m - 1;
                const int l2 = __ffs(m) - 1; m &= m - 1;
                const ull w1 = wp[l1 << 7];
                const ull w2 = wp[l2 << 7];
                fadd2(accA, w1);
                fadd2(accB, w2);
            }
            if (c & 1) {
                const int l1 = __ffs(m) - 1;
                fadd2(accA, wp[l1 << 7]);
            }
        }
        fadd2(accA, accB);

        const float ax = __int_as_float((int)(accA & 0xFFFFFFFFULL));
        const float ay = __int_as_float((int)(accA >> 32));
        rec.x = rec.x * 0.95f + ax;
        rec.y = rec.y * 0.95f + ay;

        x = xnext;
    }

    // Final trace output (B, N)
    out_trc[colv] = trc;
}

// ---------------------------------------------------------------------------
// Harness entry
// ---------------------------------------------------------------------------
extern "C" void kernel_launch(void* const* d_in, const int* in_sizes, int n_in,
                              void* d_out, int out_size) {
    const float* sig   = (const float*)d_in[0];  // (1000, 64)
    const float* w_in  = (const float*)d_in[1];  // (64, 128)
    const float* w_rec = (const float*)d_in[2];  // (128, 128)
    float* out = (float*)d_out;
    (void)in_sizes; (void)n_in; (void)out_size;

    cudaFuncSetAttribute(sim_kernel, cudaFuncAttributeMaxDynamicSharedMemorySize,
                         Nn * Nn * (int)sizeof(float));

    inp_cur_kernel<<<Tn, Nn>>>(sig, w_in);
    sim_kernel<<<GRID, THREADS, Nn * Nn * (int)sizeof(float)>>>(w_rec, out);
}

// round 5
// speedup vs baseline: 1.3562x; 1.0163x over previous
#include <cuda_runtime.h>

typedef unsigned long long ull;

// Problem constants (fixed shapes for this problem instance)
constexpr int Tn = 1000;   // timesteps
constexpr int Dd = 64;     // input dim
constexpr int Nn = 128;    // neurons
constexpr int Bb = 1000;   // batch rows

// KEY INSIGHT: the reference broadcasts x_t across all B rows and every row
// starts from identical zero state => all B rows produce IDENTICAL outputs.
// Simulate one row, then broadcast.

// Scratch
__device__ float g_inp_cur[Tn * Nn];  // per-step input currents (T, N)
__device__ float g_spk[Tn * Nn];      // compact spikes (T, N)
__device__ float g_memh[Tn * Nn];     // compact membrane (T, N)
__device__ float g_trc[Nn];           // final trace (N)

// ---------------------------------------------------------------------------
// Kernel A: tiny GEMM (1000x64 @ 64x128) -> g_inp_cur. Negligible cost.
// ---------------------------------------------------------------------------
__global__ void inp_cur_kernel(const float* __restrict__ sig,
                               const float* __restrict__ w_in) {
    int t = blockIdx.x;
    int n = threadIdx.x;
    float acc = 0.f;
#pragma unroll
    for (int d = 0; d < Dd; ++d)
        acc += sig[t * Dd + d] * w_in[d * Nn + n];
    g_inp_cur[t * Nn + n] = acc;
}

// Packed f32x2 add on raw 64-bit accumulators (1 SASS instr vs 2 FADD).
__device__ __forceinline__ void fadd2(ull& acc, ull w) {
    asm("add.rn.f32x2 %0, %0, %1;" : "+l"(acc) : "l"(w));
}

// ---------------------------------------------------------------------------
// Kernel B: single-warp simulation of ONE row (all rows are identical).
//   - Lane l owns neurons 4l..4l+3 (float4 state in registers).
//   - W_rec (128x128 fp32 = 64KB) in SMEM, loaded by 256 threads; warps 1-7
//     exit after the load. No barriers in the sim loop (ballot = sync).
//   - rec_t = trace_t @ W maintained incrementally via sparse spike masks:
//     popc-counted loop unrolled x2, dual packed-f32x2 accumulator pairs.
//   - Writes compact (T,N) spk/mem streams + final trace.
// ---------------------------------------------------------------------------
__global__ __launch_bounds__(256, 1)
void sim_kernel(const float* __restrict__ Wrec) {
    extern __shared__ float sW[];   // 64KB
    for (int i = threadIdx.x; i < (Nn * Nn) / 4; i += 256)
        reinterpret_cast<float4*>(sW)[i] =
            reinterpret_cast<const float4*>(Wrec)[i];
    __syncthreads();
    if (threadIdx.x >= 32) return;

    const int lane = threadIdx.x;
    float mem[4]  = {0.f, 0.f, 0.f, 0.f};
    float syn[4]  = {0.f, 0.f, 0.f, 0.f};
    float refr[4] = {0.f, 0.f, 0.f, 0.f};
    float rec[4]  = {0.f, 0.f, 0.f, 0.f};
    float trc[4]  = {0.f, 0.f, 0.f, 0.f};

    const float4* __restrict__ xin = reinterpret_cast<const float4*>(g_inp_cur);
    float4* __restrict__ ospk = reinterpret_cast<float4*>(g_spk);
    float4* __restrict__ omem = reinterpret_cast<float4*>(g_memh);
    // W rows as pairs of packed-f32x2: row k, lane cols -> sWu[k*32 + lane]
    const ulonglong2* __restrict__ sWu =
        reinterpret_cast<const ulonglong2*>(sW);

    float4 x = __ldg(&xin[lane]);

    for (int t = 0; t < Tn; ++t) {
        const int tn = (t + 1 < Tn) ? (t + 1) : t;
        const float4 xn = __ldg(&xin[tn * 32 + lane]);
        const float xv[4] = {x.x, x.y, x.z, x.w};

        float s[4]; bool kk[4];
#pragma unroll
        for (int j = 0; j < 4; ++j) {
            syn[j] = syn[j] * 0.8f + (xv[j] + rec[j]);
            mem[j] = mem[j] * 0.9f + syn[j] * 0.1f;
            mem[j] = (refr[j] > 0.f) ? 0.f : mem[j];
            refr[j] = fmaxf(refr[j] - 1.f, 0.f);
            kk[j] = mem[j] > 1.0f;
            s[j] = kk[j] ? 1.f : 0.f;
            mem[j] = kk[j] ? 0.f : mem[j];
            refr[j] += s[j] * 2.f;
            trc[j] = trc[j] * 0.95f + s[j];
        }

        unsigned msk[4];
#pragma unroll
        for (int j = 0; j < 4; ++j)
            msk[j] = __ballot_sync(0xFFFFFFFFu, kk[j]);

        ospk[t * 32 + lane] = make_float4(s[0], s[1], s[2], s[3]);
        omem[t * 32 + lane] = make_float4(mem[0], mem[1], mem[2], mem[3]);

        // Incremental recurrent update: rec = 0.95*rec + sum_{spiking k} W[k]
        // neuron k = 4l + j  ->  sWu[(4l+j)*32 + lane] = (sWu + j*32+lane)[l*128]
        ull aAx = 0, aAy = 0, aBx = 0, aBy = 0;
#pragma unroll
        for (int j = 0; j < 4; ++j) {
            unsigned m = msk[j];
            const ulonglong2* __restrict__ wp = sWu + j * 32 + lane;
            int c = __popc(m);
            for (int i = c >> 1; i > 0; --i) {
                const int l1 = __ffs(m) - 1; m &= m - 1;
                const int l2 = __ffs(m) - 1; m &= m - 1;
                const ulonglong2 w1 = wp[l1 * 128];
                const ulonglong2 w2 = wp[l2 * 128];
                fadd2(aAx, w1.x); fadd2(aAy, w1.y);
                fadd2(aBx, w2.x); fadd2(aBy, w2.y);
            }
            if (c & 1) {
                const int l1 = __ffs(m) - 1;
                const ulonglong2 w1 = wp[l1 * 128];
                fadd2(aAx, w1.x); fadd2(aAy, w1.y);
            }
        }
        fadd2(aAx, aBx); fadd2(aAy, aBy);

        const float a0 = __int_as_float((int)aAx);
        const float a1 = __int_as_float((int)(aAx >> 32));
        const float a2 = __int_as_float((int)aAy);
        const float a3 = __int_as_float((int)(aAy >> 32));
        rec[0] = rec[0] * 0.95f + a0;
        rec[1] = rec[1] * 0.95f + a1;
        rec[2] = rec[2] * 0.95f + a2;
        rec[3] = rec[3] * 0.95f + a3;

        x = xn;
    }

    reinterpret_cast<float4*>(g_trc)[lane] =
        make_float4(trc[0], trc[1], trc[2], trc[3]);
}

// ---------------------------------------------------------------------------
// Kernel C: broadcast compact (T,N) spk/mem to all B rows.
//   64000 threads; thread g owns one source float4 (L2-resident) and streams
//   it to 1000 destination rows (512B-coalesced warp stores, [R+imm] x8).
// ---------------------------------------------------------------------------
constexpr int BC_THREADS = 448;                       // 14 warps, 1 CTA/SM
constexpr int BC_TASKS = 2 * (Tn * Nn / 4);           // 64000 float4 sources
constexpr int BC_GRID = (BC_TASKS + BC_THREADS - 1) / BC_THREADS;  // 143

__global__ __launch_bounds__(BC_THREADS, 1)
void bcast_kernel(float* __restrict__ out) {
    const int g = blockIdx.x * BC_THREADS + threadIdx.x;
    if (g >= BC_TASKS) return;
    const int region = (g >= Tn * Nn / 4) ? 1 : 0;    // 0: spk, 1: mem
    const int src = g - region * (Tn * Nn / 4);
    const float4* __restrict__ s4 =
        reinterpret_cast<const float4*>(region ? g_memh : g_spk);
    const float4 v = __ldg(&s4[src]);
    float4* dst = reinterpret_cast<float4*>(out) +
                  (size_t)region * ((size_t)Bb * Tn * Nn / 4) + src;
#pragma unroll 8
    for (int b = 0; b < Bb; ++b) {
        *dst = v;
        dst += Tn * Nn / 4;     // next row, same (t,n) position
    }
}

// ---------------------------------------------------------------------------
// Kernel D: broadcast trace (N) to (B, N). 512KB, negligible.
// ---------------------------------------------------------------------------
__global__ void trace_kernel(float* __restrict__ out) {
    const int i = blockIdx.x * 256 + threadIdx.x;     // < B*N/4 = 32000
    const float4 v = reinterpret_cast<const float4*>(g_trc)[i & 31];
    reinterpret_cast<float4*>(out + (size_t)2 * Bb * Tn * Nn)[i] = v;
}

// ---------------------------------------------------------------------------
// Harness entry
// ---------------------------------------------------------------------------
extern "C" void kernel_launch(void* const* d_in, const int* in_sizes, int n_in,
                              void* d_out, int out_size) {
    const float* sig   = (const float*)d_in[0];  // (1000, 64)
    const float* w_in  = (const float*)d_in[1];  // (64, 128)
    const float* w_rec = (const float*)d_in[2];  // (128, 128)
    float* out = (float*)d_out;
    (void)in_sizes; (void)n_in; (void)out_size;

    cudaFuncSetAttribute(sim_kernel, cudaFuncAttributeMaxDynamicSharedMemorySize,
                         Nn * Nn * (int)sizeof(float));

    inp_cur_kernel<<<Tn, Nn>>>(sig, w_in);
    sim_kernel<<<1, 256, Nn * Nn * (int)sizeof(float)>>>(w_rec);
    bcast_kernel<<<BC_GRID, BC_THREADS>>>(out);
    trace_kernel<<<(Bb * Nn / 4) / 256, 256>>>(out);
}